// round 5
// baseline (speedup 1.0000x reference)
#include <cuda_runtime.h>
#include <math.h>

#define BB 16
#define TT 512
#define NF 32
#define DD 512
#define KD 96

typedef unsigned long long ull;

__device__ float d_U[TT * DD];     // universal sinusoidal table rows 0..511
__device__ float d_Wt[KD * DD];    // conv weight transposed to [k][d]
__device__ __align__(16) unsigned char d_flag[BB * NF];  // per-(b,n) Nyquist flag

// ---------- packed f32x2 helpers (FFMA2 is PTX-only on sm_103a) ----------
__device__ __forceinline__ ull pack2(float a, float b) {
    ull r;
    asm("mov.b64 %0, {%1, %2};" : "=l"(r)
        : "r"(__float_as_uint(a)), "r"(__float_as_uint(b)));
    return r;
}
__device__ __forceinline__ float2 unpack2(ull v) {
    unsigned lo, hi;
    asm("mov.b64 {%0, %1}, %2;" : "=r"(lo), "=r"(hi) : "l"(v));
    return make_float2(__uint_as_float(lo), __uint_as_float(hi));
}
__device__ __forceinline__ ull fma2(ull a, ull b, ull c) {
    ull d;
    asm("fma.rn.f32x2 %0, %1, %2, %3;" : "=l"(d) : "l"(a), "l"(b), "l"(c));
    return d;
}

// ================= prep: blocks 0..511 = DFT argmax, 512..575 = table/transpose =================
__global__ __launch_bounds__(128) void prep_kernel(
    const float* __restrict__ x, const float* __restrict__ conv_w)
{
    __shared__ float u0[256], u1[256];
    __shared__ float red[128];
    __shared__ float bp[128];
    __shared__ int   bk[128];
    const int tid = threadIdx.x;

    if (blockIdx.x >= 512) {
        // ---- setup part: U table (16-row strips) + W transpose ----
        int gid = ((blockIdx.x - 512) << 7) + tid;      // 0..8191
        int i  = gid & 255;                              // pair column
        int pb = gid >> 8;                               // 16-row strip id (0..31)
        const float sc = (float)(-9.210340371976184 / 512.0);
        float dv = expf((float)(2 * i) * sc);
        float S, C;
        sincosf(dv, &S, &C);
        int p0 = pb << 4;
        float s, c;
        sincosf((float)p0 * dv, &s, &c);
        float* base = d_U + p0 * DD + 2 * i;
        #pragma unroll
        for (int r = 0; r < 16; r++) {
            base[0] = s; base[1] = c;
            base += DD;
            float cn = fmaf(c, C, -s * S);
            s = fmaf(s, C, c * S);
            c = cn;
        }
        // Wt[k][d] = conv_w[d][i][h], k = h*32 + i
        for (int e = gid; e < KD * DD; e += 8192) {
            int k = e >> 9;
            int d = e & 511;
            d_Wt[e] = conv_w[d * KD + (k & 31) * 3 + (k >> 5)];
        }
        return;
    }

    // ---- DFT power argmax for (b, n) ----
    const int b = blockIdx.x >> 5;
    const int n = blockIdx.x & 31;

    float alt = 0.f;
    for (int t = tid; t < 256; t += 128) {
        float a0 = x[((b << 9) + t) * NF + n];
        float a1 = x[((b << 9) + t + 256) * NF + n];
        float e = a0 + a1, o = a0 - a1;
        u0[t] = e; u1[t] = o;
        alt += (t & 1) ? -e : e;
    }
    red[tid] = alt;
    __syncthreads();
    for (int off = 64; off > 0; off >>= 1) {
        if (tid < off) red[tid] += red[tid + off];
        __syncthreads();
    }
    const float p256 = red[0] * red[0];

    const float* y = (tid & 1) ? u1 : u0;
    const int k0 = tid, k1 = tid + 128;
    float s, c;
    sincospif((float)k0 * (1.0f / 256.0f), &s, &c);
    const ull K0 = pack2(2.f * c, 2.f * c), M0 = pack2(-2.f * c, -2.f * c);
    sincospif((float)k1 * (1.0f / 256.0f), &s, &c);
    const ull K1 = pack2(2.f * c, 2.f * c), M1 = pack2(-2.f * c, -2.f * c);

    ull acc0 = 0ull, acc1 = 0ull;
    for (int seg = 0; seg < 8; seg++) {
        int ts = seg * 32;
        int m;
        m = (k0 * (ts - 1)) & 511; sincospif((float)m * (1.0f / 256.0f), &s, &c);
        ull Pp0 = pack2(c, s), Np0 = pack2(-c, -s);
        m = (k0 * ts) & 511;       sincospif((float)m * (1.0f / 256.0f), &s, &c);
        ull Pc0 = pack2(c, s), Nc0 = pack2(-c, -s);
        m = (k1 * (ts - 1)) & 511; sincospif((float)m * (1.0f / 256.0f), &s, &c);
        ull Pp1 = pack2(c, s), Np1 = pack2(-c, -s);
        m = (k1 * ts) & 511;       sincospif((float)m * (1.0f / 256.0f), &s, &c);
        ull Pc1 = pack2(c, s), Nc1 = pack2(-c, -s);
        #pragma unroll 4
        for (int t = ts; t < ts + 32; t++) {
            float yv = y[t];
            ull YY = pack2(yv, yv);
            acc0 = fma2(YY, Pc0, acc0);
            ull Pn0 = fma2(K0, Pc0, Np0);   //  P_{t+1} = 2C*P_t - P_{t-1}
            ull Nn0 = fma2(M0, Pc0, Pp0);   // -P_{t+1}
            Pp0 = Pc0; Np0 = Nc0; Pc0 = Pn0; Nc0 = Nn0;
            acc1 = fma2(YY, Pc1, acc1);
            ull Pn1 = fma2(K1, Pc1, Np1);
            ull Nn1 = fma2(M1, Pc1, Pp1);
            Pp1 = Pc1; Np1 = Nc1; Pc1 = Pn1; Nc1 = Nn1;
        }
    }

    float2 a0v = unpack2(acc0);
    float2 a1v = unpack2(acc1);
    float pw0 = fmaf(a0v.x, a0v.x, a0v.y * a0v.y);
    float pw1 = fmaf(a1v.x, a1v.x, a1v.y * a1v.y);
    float best = pw0; int bestk = k0;
    if (pw1 > best) { best = pw1; bestk = k1; }
    bp[tid] = best; bk[tid] = bestk;
    __syncthreads();
    for (int off = 64; off > 0; off >>= 1) {
        if (tid < off) {
            float p2 = bp[tid + off]; int kk = bk[tid + off];
            if (p2 > bp[tid] || (p2 == bp[tid] && kk < bk[tid])) { bp[tid] = p2; bk[tid] = kk; }
        }
        __syncthreads();
    }
    if (tid == 0) {
        int fk = (p256 > bp[0]) ? 256 : bk[0];
        d_flag[blockIdx.x] = (fk == 256) ? 1 : 0;
    }
}

// ---------------- fused conv-GEMM: 64m x 128d tile, 4m x 8d per thread ----------------
__global__ __launch_bounds__(256, 3) void embed_kernel(
    const float* __restrict__ x, const int* __restrict__ xmark,
    float* __restrict__ out)
{
    __shared__ float slab[66 * 33];                  // x rows t0-1..t0+64, pitch 33
    __shared__ __align__(16) float Ws[48 * 128];     // W half-stage: rows r=h*16+ii

    const int tid = threadIdx.x;
    const int mt = blockIdx.x;            // 0..127
    const int nt = blockIdx.y;            // 0..3
    const int b  = mt >> 3;
    const int t0 = (mt & 7) << 6;
    const int dbase = nt << 7;

    for (int e = tid; e < 66 * 32; e += 256) {
        int r = e >> 5, i = e & 31;
        int gt = (t0 - 1 + r) & 511;      // circular within the batch
        slab[r * 33 + i] = x[((b << 9) + gt) * NF + i];
    }

    const int m0 = (tid >> 4) << 2;       // 0..60
    const int d0 = (tid & 15) << 3;       // 0..120

    ull acc[4][4];
    #pragma unroll
    for (int j = 0; j < 4; j++)
        #pragma unroll
        for (int q = 0; q < 4; q++) acc[j][q] = 0ull;

    for (int sg = 0; sg < 2; sg++) {      // feature halves i in [sg*16, sg*16+16)
        __syncthreads();
        for (int e = tid; e < 48 * 128; e += 256) {
            int r = e >> 7, d = e & 127;                 // r = h*16 + ii
            int k = ((r >> 4) << 5) + (sg << 4) + (r & 15);
            Ws[e] = d_Wt[k * DD + dbase + d];
        }
        __syncthreads();
        #pragma unroll 4
        for (int ii = 0; ii < 16; ii++) {
            int i = (sg << 4) + ii;
            const float* sp = slab + m0 * 33 + i;
            ull PR[6];                                   // rows m0..m0+5, duplicated pairs
            #pragma unroll
            for (int r = 0; r < 6; r++) { float v = sp[r * 33]; PR[r] = pack2(v, v); }
            #pragma unroll
            for (int h = 0; h < 3; h++) {
                const ulonglong2* wp =
                    reinterpret_cast<const ulonglong2*>(Ws + (h * 16 + ii) * 128 + d0);
                ulonglong2 w0 = wp[0], w1 = wp[1];
                #pragma unroll
                for (int j = 0; j < 4; j++) {
                    ull A = PR[j + h];
                    acc[j][0] = fma2(A, w0.x, acc[j][0]);
                    acc[j][1] = fma2(A, w0.y, acc[j][1]);
                    acc[j][2] = fma2(A, w1.x, acc[j][2]);
                    acc[j][3] = fma2(A, w1.y, acc[j][3]);
                }
            }
        }
    }

    // Nyquist count for this batch from flags (8 x dp4a over 32 bytes)
    const uint4 f1 = *reinterpret_cast<const uint4*>(d_flag + (b << 5));
    const uint4 f2 = *reinterpret_cast<const uint4*>(d_flag + (b << 5) + 16);
    int mb = 0;
    mb = __dp4a((int)f1.x, 0x01010101, mb);
    mb = __dp4a((int)f1.y, 0x01010101, mb);
    mb = __dp4a((int)f1.z, 0x01010101, mb);
    mb = __dp4a((int)f1.w, 0x01010101, mb);
    mb = __dp4a((int)f2.x, 0x01010101, mb);
    mb = __dp4a((int)f2.y, 0x01010101, mb);
    mb = __dp4a((int)f2.z, 0x01010101, mb);
    mb = __dp4a((int)f2.w, 0x01010101, mb);

    const float w512 = (float)(32 - mb) * 0.03125f;
    const float modd = (float)mb * 0.03125f;     // U[0,d] = 1 on odd d
    #pragma unroll
    for (int j = 0; j < 4; j++) {
        int t = t0 + m0 + j;
        int row = (b << 9) + t;
        int4 im = *reinterpret_cast<const int4*>(xmark + row * 4);
        const float* U0 = d_U + im.x * DD;
        const float* U1 = d_U + im.y * DD;
        const float* U2 = d_U + im.z * DD;
        const float* U3 = d_U + im.w * DD;
        const float* Uc = d_U + t * DD;
        int off = dbase + d0;
        #pragma unroll
        for (int g = 0; g < 2; g++) {
            int o = off + 4 * g;
            float2 pA = unpack2(acc[j][2 * g]);
            float2 pB = unpack2(acc[j][2 * g + 1]);
            float4 v0 = *reinterpret_cast<const float4*>(U0 + o);
            float4 v1 = *reinterpret_cast<const float4*>(U1 + o);
            float4 v2 = *reinterpret_cast<const float4*>(U2 + o);
            float4 v3 = *reinterpret_cast<const float4*>(U3 + o);
            float4 vc = *reinterpret_cast<const float4*>(Uc + o);
            float4 r;
            r.x = pA.x + v0.x + v1.x + v2.x + v3.x + w512 * vc.x;
            r.y = pA.y + v0.y + v1.y + v2.y + v3.y + w512 * vc.y + modd;
            r.z = pB.x + v0.z + v1.z + v2.z + v3.z + w512 * vc.z;
            r.w = pB.y + v0.w + v1.w + v2.w + v3.w + w512 * vc.w + modd;
            *reinterpret_cast<float4*>(out + row * DD + o) = r;
        }
    }
}

extern "C" void kernel_launch(void* const* d_in, const int* in_sizes, int n_in,
                              void* d_out, int out_size) {
    const float* x      = (const float*)d_in[0];
    const int*   xmark  = (const int*)d_in[1];
    const float* conv_w = (const float*)d_in[2];
    float* out = (float*)d_out;

    prep_kernel<<<576, 128>>>(x, conv_w);
    dim3 grid(128, 4);
    embed_kernel<<<grid, 256>>>(x, xmark, out);
}